// round 10
// baseline (speedup 1.0000x reference)
#include <cuda_runtime.h>
#include <cuda_bf16.h>
#include <cstdint>
#include <cstddef>

#define T_STEPS 8192
#define HIDN    1024
#define G3      3072
#define NCTA_GRU 64
#define GRU_THREADS 512   // 16 warps: one per hidden unit of the CTA's 16 units

__device__ float g_gi[(size_t)T_STEPS * G3];
__device__ float g_ys[(size_t)T_STEPS * HIDN];
__device__ unsigned g_flag[NCTA_GRU * 32];   // one flag per CTA, 128B apart

__global__ void reset_flags_kernel() {
    int i = blockIdx.x * 256 + threadIdx.x;
    if (i < NCTA_GRU * 32) g_flag[i] = 0u;
}

__global__ void dummy_kernel() { }   // shifts gru_kernel to launch index 3 for ncu

// ---------------- Phase 1: gi = x @ Wi (unchanged, verified) ----------------
__global__ __launch_bounds__(256)
void sgemm_kernel(const float* __restrict__ A, const float* __restrict__ B)
{
    const int N = G3, K = HIDN;
    __shared__ float As[16][128];
    __shared__ float Bs[16][128];
    const int tid = threadIdx.x, bx = blockIdx.x, by = blockIdx.y;
    const float* Ab = A + (size_t)by * 128 * K;
    const float* Bb = B + (size_t)bx * 128;
    float* Cb = g_gi + (size_t)by * 128 * N + (size_t)bx * 128;
    const int tcol = tid & 15, trow = tid >> 4;
    const int aRow = tid >> 2, aCol = (tid & 3) * 4;
    const int bRow = tid >> 5, bCol = (tid & 31) * 4;
    float acc[8][8];
#pragma unroll
    for (int i = 0; i < 8; i++)
#pragma unroll
        for (int j = 0; j < 8; j++) acc[i][j] = 0.f;
    float regM[8], regN[8];
    for (int k0 = 0; k0 < K; k0 += 16) {
#pragma unroll
        for (int i = 0; i < 2; i++) {
            float4 v = *reinterpret_cast<const float4*>(Ab + (size_t)(aRow + 64 * i) * K + k0 + aCol);
            As[aCol + 0][aRow + 64 * i] = v.x; As[aCol + 1][aRow + 64 * i] = v.y;
            As[aCol + 2][aRow + 64 * i] = v.z; As[aCol + 3][aRow + 64 * i] = v.w;
        }
#pragma unroll
        for (int i = 0; i < 2; i++) {
            float4 v = *reinterpret_cast<const float4*>(Bb + (size_t)(k0 + bRow + 8 * i) * N + bCol);
            *reinterpret_cast<float4*>(&Bs[bRow + 8 * i][bCol]) = v;
        }
        __syncthreads();
#pragma unroll
        for (int k = 0; k < 16; k++) {
#pragma unroll
            for (int i = 0; i < 8; i += 4)
                *reinterpret_cast<float4*>(&regM[i]) = *reinterpret_cast<float4*>(&As[k][trow * 8 + i]);
#pragma unroll
            for (int i = 0; i < 8; i += 4)
                *reinterpret_cast<float4*>(&regN[i]) = *reinterpret_cast<float4*>(&Bs[k][tcol * 8 + i]);
#pragma unroll
            for (int i = 0; i < 8; i++)
#pragma unroll
                for (int j = 0; j < 8; j++) acc[i][j] = fmaf(regM[i], regN[j], acc[i][j]);
        }
        __syncthreads();
    }
#pragma unroll
    for (int i = 0; i < 8; i++)
#pragma unroll
        for (int j = 0; j < 8; j += 4)
            *reinterpret_cast<float4*>(Cb + (size_t)(trow * 8 + i) * N + tcol * 8 + j) =
                *reinterpret_cast<const float4*>(&acc[i][j]);
}

// ---------------- Phase 2: GRU — warp-per-unit (R8 design), 64 CTAs ---------
__global__ __launch_bounds__(GRU_THREADS, 1)
void gru_kernel(const float* __restrict__ h0, const float* __restrict__ Wh,
                const float* __restrict__ bh)
{
    const int tid  = threadIdx.x;
    const int lane = tid & 31;
    const int warp = tid >> 5;                  // 0..15 = this CTA's hidden unit
    const int uu   = blockIdx.x * 16 + warp;    // global unit index

    // one-time: per-gate weight columns into registers (k = i*32 + lane)
    float wr[32], wz[32], wn[32];
#pragma unroll
    for (int i = 0; i < 32; i++) {
        size_t krow = (size_t)(i * 32 + lane) * G3;
        wr[i] = Wh[krow + uu];
        wz[i] = Wh[krow + HIDN + uu];
        wn[i] = Wh[krow + 2 * HIDN + uu];
    }
    float bt = (lane < 3) ? bh[lane * HIDN + uu] : 0.f;
    const float br = __shfl_sync(0xffffffffu, bt, 0);
    const float bz = __shfl_sync(0xffffffffu, bt, 1);
    const float bn = __shfl_sync(0xffffffffu, bt, 2);

    float hprev = h0[uu];

    unsigned* const myflag = g_flag + blockIdx.x * 32;
    const unsigned* const pollp = g_flag + (tid < NCTA_GRU ? tid : 0) * 32;

    for (int t = 0; t < T_STEPS; ++t) {
        float giv = 0.f;
        if (lane < 3) giv = __ldg(g_gi + (size_t)t * G3 + lane * HIDN + uu);

        const float* hsrc;
        if (t == 0) {
            hsrc = h0;
        } else {
            hsrc = g_ys + (size_t)(t - 1) * HIDN;
            if (tid < NCTA_GRU) {
                unsigned v;
                do {
                    asm volatile("ld.relaxed.gpu.u32 %0, [%1];"
                                 : "=r"(v) : "l"(pollp) : "memory");
                } while (v < (unsigned)t);
                asm volatile("fence.acq_rel.gpu;" ::: "memory");
            }
            __syncthreads();   // propagate acquire CTA-wide
        }

        // matvec for 3 gate columns, 12 accumulators
        float ar0 = 0.f, ar1 = 0.f, ar2 = 0.f, ar3 = 0.f;
        float az0 = 0.f, az1 = 0.f, az2 = 0.f, az3 = 0.f;
        float an0 = 0.f, an1 = 0.f, an2 = 0.f, an3 = 0.f;
#pragma unroll
        for (int i = 0; i < 32; i += 4) {
            float h0v = hsrc[(i + 0) * 32 + lane];
            float h1v = hsrc[(i + 1) * 32 + lane];
            float h2v = hsrc[(i + 2) * 32 + lane];
            float h3v = hsrc[(i + 3) * 32 + lane];
            ar0 = fmaf(wr[i + 0], h0v, ar0); az0 = fmaf(wz[i + 0], h0v, az0); an0 = fmaf(wn[i + 0], h0v, an0);
            ar1 = fmaf(wr[i + 1], h1v, ar1); az1 = fmaf(wz[i + 1], h1v, az1); an1 = fmaf(wn[i + 1], h1v, an1);
            ar2 = fmaf(wr[i + 2], h2v, ar2); az2 = fmaf(wz[i + 2], h2v, az2); an2 = fmaf(wn[i + 2], h2v, an2);
            ar3 = fmaf(wr[i + 3], h3v, ar3); az3 = fmaf(wz[i + 3], h3v, az3); an3 = fmaf(wn[i + 3], h3v, an3);
        }
        float sr = (ar0 + ar1) + (ar2 + ar3);
        float sz = (az0 + az1) + (az2 + az3);
        float sn = (an0 + an1) + (an2 + an3);
#pragma unroll
        for (int off = 16; off; off >>= 1) {
            sr += __shfl_xor_sync(0xffffffffu, sr, off);
            sz += __shfl_xor_sync(0xffffffffu, sz, off);
            sn += __shfl_xor_sync(0xffffffffu, sn, off);
        }
        float gir = __shfl_sync(0xffffffffu, giv, 0);
        float giz = __shfl_sync(0xffffffffu, giv, 1);
        float gin = __shfl_sync(0xffffffffu, giv, 2);
        float r = 0.5f + 0.5f * tanhf(0.5f * (gir + sr + br));
        float z = 0.5f + 0.5f * tanhf(0.5f * (giz + sz + bz));
        float n = tanhf(fmaf(r, sn + bn, gin));
        float hn = fmaf(z, hprev - n, n);
        hprev = hn;
        if (lane == 0) g_ys[(size_t)t * HIDN + uu] = hn;

        __syncthreads();   // all 16 stores issued (cumulative into release below)
        if (tid == 0)
            asm volatile("st.release.gpu.u32 [%0], %1;"
                         :: "l"(myflag), "r"((unsigned)(t + 1)) : "memory");
    }
}

// ---------------- Phase 3: logits = ys @ Wd + bd (unchanged) ----------------
__global__ __launch_bounds__(256)
void dense_kernel(const float* __restrict__ Wd, const float* __restrict__ bd,
                  float* __restrict__ out, int out_size)
{
    __shared__ float wd_s[HIDN * 9];
    const int tid = threadIdx.x;
    for (int i = tid; i < HIDN * 8; i += 256) wd_s[(i >> 3) * 9 + (i & 7)] = Wd[i];
    __syncthreads();
    const int warp = tid >> 5, lane = tid & 31;
    const int t = blockIdx.x * 8 + warp;
    const float* yrow = g_ys + (size_t)t * HIDN;
    float acc[8];
#pragma unroll
    for (int o = 0; o < 8; o++) acc[o] = 0.f;
#pragma unroll 4
    for (int i = 0; i < 32; i++) {
        int u = i * 32 + lane;
        float y = __ldg(yrow + u);
#pragma unroll
        for (int o = 0; o < 8; o++) acc[o] = fmaf(y, wd_s[u * 9 + o], acc[o]);
    }
#pragma unroll
    for (int o = 0; o < 8; o++) {
        float v = acc[o];
#pragma unroll
        for (int off = 16; off; off >>= 1) v += __shfl_xor_sync(0xffffffffu, v, off);
        int oi = t * 8 + o;
        if (lane == 0 && oi < out_size) out[oi] = v + bd[o];
    }
}

// ---------------- Phase 4: threefry (partitionable, verified) ---------------
__device__ __forceinline__ void tf2x32(unsigned k0, unsigned k1,
                                       unsigned x0, unsigned x1,
                                       unsigned& o0, unsigned& o1)
{
    unsigned k2 = k0 ^ k1 ^ 0x1BD11BDAu;
    x0 += k0; x1 += k1;
#define RND(r) x0 += x1; x1 = (x1 << (r)) | (x1 >> (32 - (r))); x1 ^= x0;
    RND(13) RND(15) RND(26) RND(6)
    x0 += k1; x1 += k2 + 1u;
    RND(17) RND(29) RND(16) RND(24)
    x0 += k2; x1 += k0 + 2u;
    RND(13) RND(15) RND(26) RND(6)
    x0 += k0; x1 += k1 + 3u;
    RND(17) RND(29) RND(16) RND(24)
    x0 += k1; x1 += k2 + 4u;
    RND(13) RND(15) RND(26) RND(6)
    x0 += k2; x1 += k0 + 5u;
#undef RND
    o0 = x0; o1 = x1;
}

__device__ __forceinline__ float gumbel_bits(unsigned b)
{
    float u = __uint_as_float((b >> 9) | 0x3f800000u) - 1.0f;
    u = fmaxf(u, 1.17549435e-38f);
    return -logf(-logf(u));
}

__global__ void action_kernel(const int* __restrict__ seedp,
                              float* __restrict__ out, int out_size)
{
    const int t = blockIdx.x * 256 + threadIdx.x;
    const unsigned sk0 = 0u, sk1 = (unsigned)seedp[0];
    unsigned ak0, ak1;
    tf2x32(sk0, sk1, 0u, 1u, ak0, ak1);          // act_rng = split(rng)[1]
    const unsigned i0 = 2u * (unsigned)t, i1 = i0 + 1u;
    unsigned b1, b2, c1, c2;
    tf2x32(ak0, ak1, 0u, i0, b1, b2);
    tf2x32(ak0, ak1, 0u, i1, c1, c2);
    const float s0 = gumbel_bits(b1 ^ b2) + out[(size_t)t * 8 + 0];
    const float s1 = gumbel_bits(c1 ^ c2) + out[(size_t)t * 8 + 1];
    int oi = 65536 + t;
    if (oi < out_size) out[oi] = (s1 > s0) ? 1.0f : 0.0f;
}

__global__ void finalh_kernel(float* __restrict__ out, int out_size)
{
    int i = threadIdx.x;
    int oi = 65536 + 8192 + i;
    if (oi < out_size) out[oi] = g_ys[(size_t)(T_STEPS - 1) * HIDN + i];
}

// ---------------------------------------------------------------------------
extern "C" void kernel_launch(void* const* d_in, const int* in_sizes, int n_in,
                              void* d_out, int out_size)
{
    const float* x  = (const float*)d_in[0];
    const float* h0 = (const float*)d_in[1];
    const float* Wi = (const float*)d_in[2];
    const float* Wh = (const float*)d_in[3];
    const float* bh = (const float*)d_in[4];
    const float* Wd = (const float*)d_in[5];
    const float* bd = (const float*)d_in[6];
    const int* seed = (const int*)d_in[7];
    float* out = (float*)d_out;

    reset_flags_kernel<<<8, 256>>>();      // launch 0
    sgemm_kernel<<<dim3(24, 64), 256>>>(x, Wi);   // launch 1
    dummy_kernel<<<1, 32>>>();             // launch 2 (aligns gru to ncu slot)
    gru_kernel<<<NCTA_GRU, GRU_THREADS>>>(h0, Wh, bh);   // launch 3
    dense_kernel<<<1024, 256>>>(Wd, bd, out, out_size);
    if (out_size > 65536) action_kernel<<<32, 256>>>(seed, out, out_size);
    if (out_size > 65536 + 8192) finalh_kernel<<<1, 1024>>>(out, out_size);
}

// round 12
// speedup vs baseline: 4.2996x; 4.2996x over previous
#include <cuda_runtime.h>
#include <cuda_bf16.h>
#include <cstdint>
#include <cstddef>

#define T_STEPS 8192
#define HIDN    1024
#define G3      3072
#define NCTA    128
#define GRU_THREADS 256   // 8 warps: one per hidden unit of the CTA's 8 units

__device__ float g_gi[(size_t)T_STEPS * G3];
__device__ float g_ys[(size_t)T_STEPS * HIDN];
// Two parity buffers of per-CTA 128B lines; line = 3 self-tagged float4 chunks:
// {tag,h0,h1,h2} {tag,h3,h4,h5} {tag,h6,h7,-}. tag = steps completed (uint bits).
__device__ __align__(128) float4 g_hline[2 * NCTA * 8];

__global__ void reset_lines_kernel() {
    int i = blockIdx.x * 256 + threadIdx.x;
    if (i < 2 * NCTA * 8) g_hline[i] = make_float4(0.f, 0.f, 0.f, 0.f);
}

__global__ void dummy_kernel() { }   // keeps gru_kernel at launch index 3 for ncu

// ---------------- Phase 1: gi = x @ Wi (unchanged, verified) ----------------
__global__ __launch_bounds__(256)
void sgemm_kernel(const float* __restrict__ A, const float* __restrict__ B)
{
    const int N = G3, K = HIDN;
    __shared__ float As[16][128];
    __shared__ float Bs[16][128];
    const int tid = threadIdx.x, bx = blockIdx.x, by = blockIdx.y;
    const float* Ab = A + (size_t)by * 128 * K;
    const float* Bb = B + (size_t)bx * 128;
    float* Cb = g_gi + (size_t)by * 128 * N + (size_t)bx * 128;
    const int tcol = tid & 15, trow = tid >> 4;
    const int aRow = tid >> 2, aCol = (tid & 3) * 4;
    const int bRow = tid >> 5, bCol = (tid & 31) * 4;
    float acc[8][8];
#pragma unroll
    for (int i = 0; i < 8; i++)
#pragma unroll
        for (int j = 0; j < 8; j++) acc[i][j] = 0.f;
    float regM[8], regN[8];
    for (int k0 = 0; k0 < K; k0 += 16) {
#pragma unroll
        for (int i = 0; i < 2; i++) {
            float4 v = *reinterpret_cast<const float4*>(Ab + (size_t)(aRow + 64 * i) * K + k0 + aCol);
            As[aCol + 0][aRow + 64 * i] = v.x; As[aCol + 1][aRow + 64 * i] = v.y;
            As[aCol + 2][aRow + 64 * i] = v.z; As[aCol + 3][aRow + 64 * i] = v.w;
        }
#pragma unroll
        for (int i = 0; i < 2; i++) {
            float4 v = *reinterpret_cast<const float4*>(Bb + (size_t)(k0 + bRow + 8 * i) * N + bCol);
            *reinterpret_cast<float4*>(&Bs[bRow + 8 * i][bCol]) = v;
        }
        __syncthreads();
#pragma unroll
        for (int k = 0; k < 16; k++) {
#pragma unroll
            for (int i = 0; i < 8; i += 4)
                *reinterpret_cast<float4*>(&regM[i]) = *reinterpret_cast<float4*>(&As[k][trow * 8 + i]);
#pragma unroll
            for (int i = 0; i < 8; i += 4)
                *reinterpret_cast<float4*>(&regN[i]) = *reinterpret_cast<float4*>(&Bs[k][tcol * 8 + i]);
#pragma unroll
            for (int i = 0; i < 8; i++)
#pragma unroll
                for (int j = 0; j < 8; j++) acc[i][j] = fmaf(regM[i], regN[j], acc[i][j]);
        }
        __syncthreads();
    }
#pragma unroll
    for (int i = 0; i < 8; i++)
#pragma unroll
        for (int j = 0; j < 8; j += 4)
            *reinterpret_cast<float4*>(Cb + (size_t)(trow * 8 + i) * N + tcol * 8 + j) =
                *reinterpret_cast<const float4*>(&acc[i][j]);
}

// ---------------- Phase 2: GRU — R8 compute + fused tag+data sync -----------
__device__ __forceinline__ float4 ldrelax4(const float4* p) {
    float4 v;
    asm volatile("ld.relaxed.gpu.v4.f32 {%0,%1,%2,%3}, [%4];"
                 : "=f"(v.x), "=f"(v.y), "=f"(v.z), "=f"(v.w) : "l"(p) : "memory");
    return v;
}
__device__ __forceinline__ void strelax4(float4* p, float4 v) {
    asm volatile("st.relaxed.gpu.v4.f32 [%0], {%1,%2,%3,%4};"
                 :: "l"(p), "f"(v.x), "f"(v.y), "f"(v.z), "f"(v.w) : "memory");
}

__global__ __launch_bounds__(GRU_THREADS, 1)
void gru_kernel(const float* __restrict__ h0, const float* __restrict__ Wh,
                const float* __restrict__ bh)
{
    __shared__ float sh[HIDN];     // current h row
    __shared__ float hout[8];      // this CTA's new h
    const int tid  = threadIdx.x;
    const int lane = tid & 31;
    const int warp = tid >> 5;                 // 0..7 = this CTA's hidden unit
    const int uu   = blockIdx.x * 8 + warp;

    // one-time: per-gate weight columns into registers (k = i*32 + lane)
    float wr[32], wz[32], wn[32];
#pragma unroll
    for (int i = 0; i < 32; i++) {
        size_t krow = (size_t)(i * 32 + lane) * G3;
        wr[i] = Wh[krow + uu];
        wz[i] = Wh[krow + HIDN + uu];
        wn[i] = Wh[krow + 2 * HIDN + uu];
    }
    float bt = (lane < 3) ? bh[lane * HIDN + uu] : 0.f;
    const float br = __shfl_sync(0xffffffffu, bt, 0);
    const float bz = __shfl_sync(0xffffffffu, bt, 1);
    const float bn = __shfl_sync(0xffffffffu, bt, 2);

    float hprev = h0[uu];

    for (int t = 0; t < T_STEPS; ++t) {
        // gi prefetch (independent of recurrence) — lanes 0..2 = r,z,n
        float giv = 0.f;
        if (lane < 3) giv = __ldg(g_gi + (size_t)t * G3 + lane * HIDN + uu);

        // fetch h(t-1): tid<128 each handles one producer CTA's line
        if (tid < NCTA) {
            float* d = sh + tid * 8;
            if (t == 0) {
                float4 a = *reinterpret_cast<const float4*>(h0 + tid * 8);
                float4 b = *reinterpret_cast<const float4*>(h0 + tid * 8 + 4);
                d[0] = a.x; d[1] = a.y; d[2] = a.z; d[3] = a.w;
                d[4] = b.x; d[5] = b.y; d[6] = b.z; d[7] = b.w;
            } else {
                const float4* lp = g_hline + ((((t + 1) & 1) * NCTA) + tid) * 8;
                const unsigned tgt = (unsigned)t;
                float4 c0, c1, c2;
                do {
                    c0 = ldrelax4(lp); c1 = ldrelax4(lp + 1); c2 = ldrelax4(lp + 2);
                } while (__float_as_uint(c0.x) < tgt ||
                         __float_as_uint(c1.x) < tgt ||
                         __float_as_uint(c2.x) < tgt);
                d[0] = c0.y; d[1] = c0.z; d[2] = c0.w;
                d[3] = c1.y; d[4] = c1.z; d[5] = c1.w;
                d[6] = c2.y; d[7] = c2.z;
            }
        }
        __syncthreads();

        // matvec for 3 gate columns, 12 accumulators, h from SMEM (no conflicts)
        float ar0 = 0.f, ar1 = 0.f, ar2 = 0.f, ar3 = 0.f;
        float az0 = 0.f, az1 = 0.f, az2 = 0.f, az3 = 0.f;
        float an0 = 0.f, an1 = 0.f, an2 = 0.f, an3 = 0.f;
#pragma unroll
        for (int i = 0; i < 32; i += 4) {
            float h0v = sh[(i + 0) * 32 + lane];
            float h1v = sh[(i + 1) * 32 + lane];
            float h2v = sh[(i + 2) * 32 + lane];
            float h3v = sh[(i + 3) * 32 + lane];
            ar0 = fmaf(wr[i + 0], h0v, ar0); az0 = fmaf(wz[i + 0], h0v, az0); an0 = fmaf(wn[i + 0], h0v, an0);
            ar1 = fmaf(wr[i + 1], h1v, ar1); az1 = fmaf(wz[i + 1], h1v, az1); an1 = fmaf(wn[i + 1], h1v, an1);
            ar2 = fmaf(wr[i + 2], h2v, ar2); az2 = fmaf(wz[i + 2], h2v, az2); an2 = fmaf(wn[i + 2], h2v, an2);
            ar3 = fmaf(wr[i + 3], h3v, ar3); az3 = fmaf(wz[i + 3], h3v, az3); an3 = fmaf(wn[i + 3], h3v, an3);
        }
        float sr = (ar0 + ar1) + (ar2 + ar3);
        float sz = (az0 + az1) + (az2 + az3);
        float sn = (an0 + an1) + (an2 + an3);
#pragma unroll
        for (int off = 16; off; off >>= 1) {
            sr += __shfl_xor_sync(0xffffffffu, sr, off);
            sz += __shfl_xor_sync(0xffffffffu, sz, off);
            sn += __shfl_xor_sync(0xffffffffu, sn, off);
        }
        float gir = __shfl_sync(0xffffffffu, giv, 0);
        float giz = __shfl_sync(0xffffffffu, giv, 1);
        float gin = __shfl_sync(0xffffffffu, giv, 2);
        float r = 0.5f + 0.5f * tanhf(0.5f * (gir + sr + br));
        float z = 0.5f + 0.5f * tanhf(0.5f * (giz + sz + bz));
        float n = tanhf(fmaf(r, sn + bn, gin));
        float hn = fmaf(z, hprev - n, n);
        hprev = hn;
        if (lane == 0) {
            hout[warp] = hn;
            g_ys[(size_t)t * HIDN + uu] = hn;   // weak store; read after kernel end
        }
        __syncthreads();

        // publish: 3 lanes store self-tagged chunks in parallel (one STG.128 each)
        if (tid < 3) {
            float4* lp = g_hline + (((t & 1) * NCTA) + blockIdx.x) * 8 + tid;
            const float tag = __uint_as_float((unsigned)(t + 1));
            float a = hout[tid * 3 + 0];
            float b = (tid < 2) ? hout[tid * 3 + 1] : hout[7];
            float c = (tid < 2) ? hout[tid * 3 + 2] : 0.f;
            // chunks: {h0,h1,h2} {h3,h4,h5} {h6,h7,-}
            strelax4(lp, make_float4(tag, a, b, c));
        }
    }
}

// ---------------- Phase 3: logits = ys @ Wd + bd (unchanged) ----------------
__global__ __launch_bounds__(256)
void dense_kernel(const float* __restrict__ Wd, const float* __restrict__ bd,
                  float* __restrict__ out, int out_size)
{
    __shared__ float wd_s[HIDN * 9];
    const int tid = threadIdx.x;
    for (int i = tid; i < HIDN * 8; i += 256) wd_s[(i >> 3) * 9 + (i & 7)] = Wd[i];
    __syncthreads();
    const int warp = tid >> 5, lane = tid & 31;
    const int t = blockIdx.x * 8 + warp;
    const float* yrow = g_ys + (size_t)t * HIDN;
    float acc[8];
#pragma unroll
    for (int o = 0; o < 8; o++) acc[o] = 0.f;
#pragma unroll 4
    for (int i = 0; i < 32; i++) {
        int u = i * 32 + lane;
        float y = __ldg(yrow + u);
#pragma unroll
        for (int o = 0; o < 8; o++) acc[o] = fmaf(y, wd_s[u * 9 + o], acc[o]);
    }
#pragma unroll
    for (int o = 0; o < 8; o++) {
        float v = acc[o];
#pragma unroll
        for (int off = 16; off; off >>= 1) v += __shfl_xor_sync(0xffffffffu, v, off);
        int oi = t * 8 + o;
        if (lane == 0 && oi < out_size) out[oi] = v + bd[o];
    }
}

// ---------------- Phase 4: threefry (partitionable, verified) ---------------
__device__ __forceinline__ void tf2x32(unsigned k0, unsigned k1,
                                       unsigned x0, unsigned x1,
                                       unsigned& o0, unsigned& o1)
{
    unsigned k2 = k0 ^ k1 ^ 0x1BD11BDAu;
    x0 += k0; x1 += k1;
#define RND(r) x0 += x1; x1 = (x1 << (r)) | (x1 >> (32 - (r))); x1 ^= x0;
    RND(13) RND(15) RND(26) RND(6)
    x0 += k1; x1 += k2 + 1u;
    RND(17) RND(29) RND(16) RND(24)
    x0 += k2; x1 += k0 + 2u;
    RND(13) RND(15) RND(26) RND(6)
    x0 += k0; x1 += k1 + 3u;
    RND(17) RND(29) RND(16) RND(24)
    x0 += k1; x1 += k2 + 4u;
    RND(13) RND(15) RND(26) RND(6)
    x0 += k2; x1 += k0 + 5u;
#undef RND
    o0 = x0; o1 = x1;
}

__device__ __forceinline__ float gumbel_bits(unsigned b)
{
    float u = __uint_as_float((b >> 9) | 0x3f800000u) - 1.0f;
    u = fmaxf(u, 1.17549435e-38f);
    return -logf(-logf(u));
}

__global__ void action_kernel(const int* __restrict__ seedp,
                              float* __restrict__ out, int out_size)
{
    const int t = blockIdx.x * 256 + threadIdx.x;
    const unsigned sk0 = 0u, sk1 = (unsigned)seedp[0];
    unsigned ak0, ak1;
    tf2x32(sk0, sk1, 0u, 1u, ak0, ak1);          // act_rng = split(rng)[1]
    const unsigned i0 = 2u * (unsigned)t, i1 = i0 + 1u;
    unsigned b1, b2, c1, c2;
    tf2x32(ak0, ak1, 0u, i0, b1, b2);
    tf2x32(ak0, ak1, 0u, i1, c1, c2);
    const float s0 = gumbel_bits(b1 ^ b2) + out[(size_t)t * 8 + 0];
    const float s1 = gumbel_bits(c1 ^ c2) + out[(size_t)t * 8 + 1];
    int oi = 65536 + t;
    if (oi < out_size) out[oi] = (s1 > s0) ? 1.0f : 0.0f;
}

__global__ void finalh_kernel(float* __restrict__ out, int out_size)
{
    int i = threadIdx.x;
    int oi = 65536 + 8192 + i;
    if (oi < out_size) out[oi] = g_ys[(size_t)(T_STEPS - 1) * HIDN + i];
}

// ---------------------------------------------------------------------------
extern "C" void kernel_launch(void* const* d_in, const int* in_sizes, int n_in,
                              void* d_out, int out_size)
{
    const float* x  = (const float*)d_in[0];
    const float* h0 = (const float*)d_in[1];
    const float* Wi = (const float*)d_in[2];
    const float* Wh = (const float*)d_in[3];
    const float* bh = (const float*)d_in[4];
    const float* Wd = (const float*)d_in[5];
    const float* bd = (const float*)d_in[6];
    const int* seed = (const int*)d_in[7];
    float* out = (float*)d_out;

    reset_lines_kernel<<<8, 256>>>();                  // launch 0
    sgemm_kernel<<<dim3(24, 64), 256>>>(x, Wi);        // launch 1
    dummy_kernel<<<1, 32>>>();                         // launch 2
    gru_kernel<<<NCTA, GRU_THREADS>>>(h0, Wh, bh);     // launch 3 (ncu slot)
    dense_kernel<<<1024, 256>>>(Wd, bd, out, out_size);
    if (out_size > 65536) action_kernel<<<32, 256>>>(seed, out, out_size);
    if (out_size > 65536 + 8192) finalh_kernel<<<1, 1024>>>(out, out_size);
}